// round 2
// baseline (speedup 1.0000x reference)
#include <cuda_runtime.h>
#include <cstddef>
#include <math.h>

// ---------------- problem constants ----------------
constexpr int EG  = 300000;   // edges
constexpr int TT  = 1000000;  // triplets
constexpr int NA  = 20000;    // atoms
constexpr int NM  = 1000;     // molecules
constexpr int E   = 128;      // embedding
constexpr int NR  = 6;
constexpr int NABF= 7;
constexpr int NB  = 3;

// ---------------- scratch (carved from one static buffer) ----------------
constexpr size_t OFF_RBF  = 0;                                  // EG*6
constexpr size_t OFF_ABF  = OFF_RBF  + (size_t)EG*6;            // TT*7
constexpr size_t OFF_CAT  = OFF_ABF  + (size_t)TT*7;            // EG*384
constexpr size_t OFF_X    = OFF_CAT  + (size_t)EG*384;          // EG*128
constexpr size_t OFF_XJI  = OFF_X    + (size_t)EG*128;
constexpr size_t OFF_XKJ  = OFF_XJI  + (size_t)EG*128;
constexpr size_t OFF_AGGR = OFF_XKJ  + (size_t)EG*128;
constexpr size_t OFF_IRBF = OFF_AGGR + (size_t)EG*128;
constexpr size_t OFF_TMPE = OFF_IRBF + (size_t)EG*128;
constexpr size_t OFF_PA   = OFF_TMPE + (size_t)EG*128;          // NA*128
constexpr size_t OFF_HAT  = OFF_PA   + (size_t)NA*128;
constexpr size_t OFF_ROUT = OFF_HAT  + (size_t)NA*128;
constexpr size_t OFF_RSING= OFF_ROUT + (size_t)NA*128;
constexpr size_t OFF_STMP = OFF_RSING+ (size_t)NA*128;
constexpr size_t OFF_X0   = OFF_STMP + (size_t)NA*128;
constexpr size_t TOTAL_F  = OFF_X0   + (size_t)NA*128;

__device__ float g_buf[TOTAL_F];

__device__ __forceinline__ float silu_f(float x) {
    return x / (1.f + __expf(-x));
}

// ---------------- RBF over edges ----------------
__global__ void rbf_kernel(const float* __restrict__ R,
                           const int* __restrict__ idx_i,
                           const int* __restrict__ idx_j,
                           float* __restrict__ rbf)
{
    const float PI_F = 3.14159265358979323846f;
    const float c = sqrtf(2.f / 5.f);
    for (int e = blockIdx.x * blockDim.x + threadIdx.x; e < EG;
         e += gridDim.x * blockDim.x) {
        int i = idx_i[e], j = idx_j[e];
        float dx = R[3*i+0] - R[3*j+0];
        float dy = R[3*i+1] - R[3*j+1];
        float dz = R[3*i+2] - R[3*j+2];
        float d = sqrtf(dx*dx + dy*dy + dz*dz);
        d = fmaxf(d, 1e-2f);
        float inv = 1.f / d;
        float arg = d * (PI_F / 5.f);
        #pragma unroll
        for (int r = 0; r < NR; r++)
            rbf[(size_t)e*NR + r] = c * sinf((float)(r+1) * arg) * inv;
    }
}

// ---------------- ABF over triplets ----------------
__global__ void abf_kernel(const float* __restrict__ cosik,
                           float* __restrict__ abf)
{
    for (int t = blockIdx.x * blockDim.x + threadIdx.x; t < TT;
         t += gridDim.x * blockDim.x) {
        float cth = fminf(1.f, fmaxf(-1.f, cosik[t]));
        float th = acosf(cth);
        #pragma unroll
        for (int k = 0; k < NABF; k++)
            abf[(size_t)t*NABF + k] = cosf((float)k * th);
    }
}

// ---------------- build [x0_i | x0_j | silu(rbf@W_rbf_emb)] ----------------
__global__ __launch_bounds__(128) void buildcat_kernel(
    const int* __restrict__ Z,
    const int* __restrict__ idx_i,
    const int* __restrict__ idx_j,
    const float* __restrict__ emb,
    const float* __restrict__ Wrbf,       // [6,128]
    const float* __restrict__ rbf,
    float* __restrict__ cat)
{
    __shared__ float ws[NR*E];
    for (int k = threadIdx.x; k < NR*E; k += 128) ws[k] = Wrbf[k];
    __syncthreads();
    int t = threadIdx.x;
    for (int e = blockIdx.x; e < EG; e += gridDim.x) {
        int ai = idx_i[e], aj = idx_j[e];
        float s = 0.f;
        #pragma unroll
        for (int r = 0; r < NR; r++)
            s += rbf[(size_t)e*NR + r] * ws[r*E + t];
        s = silu_f(s);
        size_t base = (size_t)e * 384;
        cat[base + t]       = emb[(size_t)Z[ai]*E + t];
        cat[base + 128 + t] = emb[(size_t)Z[aj]*E + t];
        cat[base + 256 + t] = s;
    }
}

// ---------------- x0 gather (atoms) ----------------
__global__ void x0_kernel(const int* __restrict__ Z,
                          const float* __restrict__ emb,
                          float* __restrict__ x0)
{
    size_t total = (size_t)NA * E;
    for (size_t idx = blockIdx.x * (size_t)blockDim.x + threadIdx.x; idx < total;
         idx += (size_t)gridDim.x * blockDim.x) {
        int a = (int)(idx >> 7);
        int c = (int)(idx & 127);
        x0[idx] = emb[(size_t)Z[a]*E + c];
    }
}

// ---------------- C[M,128] = (rbf[M,6] @ W[6,128]) (* mul) ----------------
__global__ __launch_bounds__(256) void rbfmat_kernel(
    const float* __restrict__ rbf,
    const float* __restrict__ W,          // [6,128]
    const float* __restrict__ mulp,       // optional [M,128]
    float* __restrict__ C, int M)
{
    __shared__ float ws[NR*E];
    for (int k = threadIdx.x; k < NR*E; k += 256) ws[k] = W[k];
    __syncthreads();
    size_t total = (size_t)M * E;
    for (size_t idx = blockIdx.x * (size_t)blockDim.x + threadIdx.x; idx < total;
         idx += (size_t)gridDim.x * blockDim.x) {
        int m = (int)(idx >> 7);
        int c = (int)(idx & 127);
        const float* rr = &rbf[(size_t)m * NR];
        float s = rr[0]*ws[c] + rr[1]*ws[E+c] + rr[2]*ws[2*E+c]
                + rr[3]*ws[3*E+c] + rr[4]*ws[4*E+c] + rr[5]*ws[5*E+c];
        if (mulp) s *= mulp[idx];
        C[idx] = s;
    }
}

// ---------------- generic SGEMM: C[M,128] = epi(A[M,K] @ W[K,128]) ----------------
// epi: (+bias) -> (silu if act) -> (*mulp) -> (+addp)
__global__ __launch_bounds__(256) void gemm128_kernel(
    const float* __restrict__ A,
    const float* __restrict__ W,
    const float* __restrict__ bias,
    const float* __restrict__ mulp,
    const float* __restrict__ addp,
    float* __restrict__ C,
    int M, int K, int act)
{
    __shared__ float As[128*17];
    __shared__ float Ws[16*128];
    int tid = threadIdx.x;
    int bm = blockIdx.x * 128;
    int r0 = (tid >> 4) << 3;    // 0..120 step 8
    int c0 = (tid & 15) << 3;    // 0..120 step 8

    float acc[8][8];
    #pragma unroll
    for (int i = 0; i < 8; i++)
        #pragma unroll
        for (int j = 0; j < 8; j++) acc[i][j] = 0.f;

    int lr = tid >> 2;           // 0..63
    int lc = (tid & 3) << 2;     // 0,4,8,12
    int wk = tid >> 4;           // 0..15
    int wc = (tid & 15) << 3;    // 0..120

    for (int kt = 0; kt < K; kt += 16) {
        #pragma unroll
        for (int h = 0; h < 2; h++) {
            int row = lr + h*64;
            int grow = bm + row;
            float4 v = make_float4(0.f,0.f,0.f,0.f);
            if (grow < M) v = *(const float4*)&A[(size_t)grow*K + kt + lc];
            As[row*17 + lc + 0] = v.x;
            As[row*17 + lc + 1] = v.y;
            As[row*17 + lc + 2] = v.z;
            As[row*17 + lc + 3] = v.w;
        }
        {
            const float4* src = (const float4*)&W[(size_t)(kt+wk)*128 + wc];
            float4 v0 = src[0];
            float4 v1 = src[1];
            *(float4*)&Ws[wk*128 + wc]     = v0;
            *(float4*)&Ws[wk*128 + wc + 4] = v1;
        }
        __syncthreads();
        #pragma unroll
        for (int kk = 0; kk < 16; kk++) {
            float a[8], w[8];
            #pragma unroll
            for (int i = 0; i < 8; i++) a[i] = As[(r0+i)*17 + kk];
            float4 w0 = *(float4*)&Ws[kk*128 + c0];
            float4 w1 = *(float4*)&Ws[kk*128 + c0 + 4];
            w[0]=w0.x; w[1]=w0.y; w[2]=w0.z; w[3]=w0.w;
            w[4]=w1.x; w[5]=w1.y; w[6]=w1.z; w[7]=w1.w;
            #pragma unroll
            for (int i = 0; i < 8; i++)
                #pragma unroll
                for (int j = 0; j < 8; j++)
                    acc[i][j] += a[i] * w[j];
        }
        __syncthreads();
    }

    float bv[8];
    #pragma unroll
    for (int j = 0; j < 8; j++) bv[j] = bias ? bias[c0+j] : 0.f;

    #pragma unroll
    for (int i = 0; i < 8; i++) {
        int grow = bm + r0 + i;
        if (grow < M) {
            size_t base = (size_t)grow*128 + c0;
            #pragma unroll
            for (int j = 0; j < 8; j++) {
                float v = acc[i][j] + bv[j];
                if (act) v = silu_f(v);
                if (mulp) v *= mulp[base + j];
                if (addp) v += addp[base + j];
                C[base + j] = v;
            }
        }
    }
}

// ---------------- triplet messages + scatter to edges ----------------
__global__ __launch_bounds__(256) void triplet_kernel(
    const float* __restrict__ xkj,
    const float* __restrict__ abf,
    const int* __restrict__ idx_kj,
    const int* __restrict__ idx_ji,
    const float* __restrict__ Wabf,       // [7,128]
    float* __restrict__ aggr)
{
    __shared__ float ws[NABF*E];
    for (int k = threadIdx.x; k < NABF*E; k += 256) ws[k] = Wabf[k];
    __syncthreads();
    int lane = threadIdx.x & 31;
    int warp = (blockIdx.x * 256 + threadIdx.x) >> 5;
    int nwarps = (gridDim.x * 256) >> 5;
    int c = lane << 2;
    for (int t = warp; t < TT; t += nwarps) {
        int ekj = idx_kj[t];
        int eji = idx_ji[t];
        const float* ab = &abf[(size_t)t * NABF];
        float a0=ab[0], a1=ab[1], a2=ab[2], a3=ab[3], a4=ab[4], a5=ab[5], a6=ab[6];
        float4 xv = *(const float4*)&xkj[(size_t)ekj*128 + c];
        float m[4];
        #pragma unroll
        for (int j = 0; j < 4; j++) {
            int cc = c + j;
            m[j] = a0*ws[cc] + a1*ws[E+cc] + a2*ws[2*E+cc] + a3*ws[3*E+cc]
                 + a4*ws[4*E+cc] + a5*ws[5*E+cc] + a6*ws[6*E+cc];
        }
        float* dst = &aggr[(size_t)eji*128 + c];
        atomicAdd(dst+0, xv.x * m[0]);
        atomicAdd(dst+1, xv.y * m[1]);
        atomicAdd(dst+2, xv.z * m[2]);
        atomicAdd(dst+3, xv.w * m[3]);
    }
}

// ---------------- elementwise add: a += b ----------------
__global__ void add_kernel(float* __restrict__ a, const float* __restrict__ b, size_t n4)
{
    float4* a4 = (float4*)a;
    const float4* b4 = (const float4*)b;
    for (size_t i = blockIdx.x * (size_t)blockDim.x + threadIdx.x; i < n4;
         i += (size_t)gridDim.x * blockDim.x) {
        float4 x = a4[i], y = b4[i];
        x.x += y.x; x.y += y.y; x.z += y.z; x.w += y.w;
        a4[i] = x;
    }
}

// ---------------- scatter edges -> atoms (segment sum over idx_i) ----------------
__global__ void scat_atoms_kernel(const float* __restrict__ g,
                                  const int* __restrict__ idxi,
                                  float* __restrict__ pa)
{
    size_t total = (size_t)EG * 32;
    for (size_t idx = blockIdx.x * (size_t)blockDim.x + threadIdx.x; idx < total;
         idx += (size_t)gridDim.x * blockDim.x) {
        int e = (int)(idx >> 5);
        int c = (int)(idx & 31) << 2;
        int a = idxi[e];
        float4 v = *(const float4*)&g[(size_t)e*128 + c];
        float* dst = &pa[(size_t)a*128 + c];
        atomicAdd(dst+0, v.x);
        atomicAdd(dst+1, v.y);
        atomicAdd(dst+2, v.z);
        atomicAdd(dst+3, v.w);
    }
}

// ---------------- final: molecules = coef_mp*seg(resout) + coef_sg*seg(ressing) ----------------
__global__ void final_kernel(const float* __restrict__ ro,
                             const float* __restrict__ rs,
                             const int* __restrict__ bseg,
                             const float* __restrict__ cmp_p,
                             const float* __restrict__ csg_p,
                             float* __restrict__ out)
{
    float cmp = cmp_p[0], csg = csg_p[0];
    size_t total = (size_t)NA * 32;
    for (size_t idx = blockIdx.x * (size_t)blockDim.x + threadIdx.x; idx < total;
         idx += (size_t)gridDim.x * blockDim.x) {
        int a = (int)(idx >> 5);
        int c = (int)(idx & 31) << 2;
        int m = bseg[a];
        float4 o = *(const float4*)&ro[(size_t)a*128 + c];
        float4 s = *(const float4*)&rs[(size_t)a*128 + c];
        float* dst = &out[(size_t)m*128 + c];
        atomicAdd(dst+0, cmp*o.x + csg*s.x);
        atomicAdd(dst+1, cmp*o.y + csg*s.y);
        atomicAdd(dst+2, cmp*o.z + csg*s.z);
        atomicAdd(dst+3, cmp*o.w + csg*s.w);
    }
}

// ---------------- host orchestration ----------------
extern "C" void kernel_launch(void* const* d_in, const int* in_sizes, int n_in,
                              void* d_out, int out_size)
{
    const int*   Z      = (const int*)  d_in[0];
    const float* R      = (const float*)d_in[1];
    const int*   bseg   = (const int*)  d_in[2];
    const int*   idx_i  = (const int*)  d_in[3];
    const int*   idx_j  = (const int*)  d_in[4];
    const int*   idx_kj = (const int*)  d_in[5];
    const int*   idx_ji = (const int*)  d_in[6];
    const float* cosik  = (const float*)d_in[7];
    const float* emb    = (const float*)d_in[8];
    const float* Wrbf   = (const float*)d_in[9];
    const float* Wemb   = (const float*)d_in[10];
    const float* bemb   = (const float*)d_in[11];
    const float* Worbf  = (const float*)d_in[12];
    const float* Wo1    = (const float*)d_in[13];
    const float* bo1    = (const float*)d_in[14];
    const float* Wout   = (const float*)d_in[15];
    const float* Wid1   = (const float*)d_in[16];
    const float* bid1   = (const float*)d_in[17];
    const float* Wid2   = (const float*)d_in[18];
    const float* Wji    = (const float*)d_in[19];
    const float* bji    = (const float*)d_in[20];
    const float* Wkj    = (const float*)d_in[21];
    const float* bkj    = (const float*)d_in[22];
    const float* Wirbf  = (const float*)d_in[23];
    const float* Wabf   = (const float*)d_in[24];
    const float* Wres   = (const float*)d_in[25];
    const float* bres   = (const float*)d_in[26];
    const float* cmp    = (const float*)d_in[27];
    const float* csg    = (const float*)d_in[28];
    float* out = (float*)d_out;

    float* buf = nullptr;
    cudaGetSymbolAddress((void**)&buf, g_buf);
    float* RBF   = buf + OFF_RBF;
    float* ABF   = buf + OFF_ABF;
    float* CAT   = buf + OFF_CAT;
    float* X     = buf + OFF_X;
    float* XJI   = buf + OFF_XJI;
    float* XKJ   = buf + OFF_XKJ;
    float* AGGR  = buf + OFF_AGGR;
    float* IRBF  = buf + OFF_IRBF;
    float* TMPE  = buf + OFF_TMPE;
    float* PA    = buf + OFF_PA;
    float* HAT   = buf + OFF_HAT;
    float* ROUT  = buf + OFF_ROUT;
    float* RSING = buf + OFF_RSING;
    float* STMP  = buf + OFF_STMP;
    float* X0    = buf + OFF_X0;

    const int GE = (EG + 127) / 128;   // 2344
    const int GA = (NA + 127) / 128;   // 157

    // basis functions
    rbf_kernel<<<1024, 256>>>(R, idx_i, idx_j, RBF);
    abf_kernel<<<2048, 256>>>(cosik, ABF);

    // embedding block
    buildcat_kernel<<<4096, 128>>>(Z, idx_i, idx_j, emb, Wrbf, RBF, CAT);
    x0_kernel<<<2048, 256>>>(Z, emb, X0);
    gemm128_kernel<<<GE, 256>>>(CAT, Wemb, bemb, nullptr, nullptr, X, EG, 384, 1);

    // output block 0
    rbfmat_kernel<<<2048, 256>>>(RBF, Worbf, X, TMPE, EG);
    cudaMemsetAsync(PA, 0, (size_t)NA*E*sizeof(float));
    scat_atoms_kernel<<<2048, 256>>>(TMPE, idx_i, PA);
    gemm128_kernel<<<GA, 256>>>(PA, Wo1, bo1, nullptr, nullptr, HAT, NA, 128, 1);
    gemm128_kernel<<<GA, 256>>>(HAT, Wout, nullptr, nullptr, nullptr, ROUT, NA, 128, 0);

    // identity block 0 (input = x0)
    gemm128_kernel<<<GA, 256>>>(X0, Wid1, bid1, nullptr, nullptr, STMP, NA, 128, 1);
    gemm128_kernel<<<GA, 256>>>(STMP, Wid2, nullptr, nullptr, nullptr, RSING, NA, 128, 0);

    for (int i = 0; i < NB; i++) {
        // interaction block i
        gemm128_kernel<<<GE, 256>>>(X, Wji + (size_t)i*E*E, bji + (size_t)i*E,
                                    nullptr, nullptr, XJI, EG, 128, 1);
        rbfmat_kernel<<<2048, 256>>>(RBF, Wirbf + (size_t)i*NR*E, nullptr, IRBF, EG);
        gemm128_kernel<<<GE, 256>>>(X, Wkj + (size_t)i*E*E, bkj + (size_t)i*E,
                                    IRBF, nullptr, XKJ, EG, 128, 1);
        cudaMemsetAsync(AGGR, 0, (size_t)EG*E*sizeof(float));
        triplet_kernel<<<2048, 256>>>(XKJ, ABF, idx_kj, idx_ji,
                                      Wabf + (size_t)i*NABF*E, AGGR);
        add_kernel<<<2048, 256>>>(XJI, AGGR, (size_t)EG*E/4);   // XJI = h
        gemm128_kernel<<<GE, 256>>>(XJI, Wres + (size_t)i*E*E, bres + (size_t)i*E,
                                    nullptr, XJI, X, EG, 128, 1); // x = h + silu(h@W+b)

        // output block i+1
        rbfmat_kernel<<<2048, 256>>>(RBF, Worbf + (size_t)(i+1)*NR*E, X, TMPE, EG);
        cudaMemsetAsync(PA, 0, (size_t)NA*E*sizeof(float));
        scat_atoms_kernel<<<2048, 256>>>(TMPE, idx_i, PA);
        gemm128_kernel<<<GA, 256>>>(PA, Wo1 + (size_t)(i+1)*E*E, bo1 + (size_t)(i+1)*E,
                                    nullptr, nullptr, HAT, NA, 128, 1);
        gemm128_kernel<<<GA, 256>>>(HAT, Wout + (size_t)(i+1)*E*E,
                                    nullptr, nullptr, ROUT, ROUT, NA, 128, 0);

        // identity block i+1
        gemm128_kernel<<<GA, 256>>>(RSING, Wid1 + (size_t)(i+1)*E*E, bid1 + (size_t)(i+1)*E,
                                    nullptr, nullptr, STMP, NA, 128, 1);
        gemm128_kernel<<<GA, 256>>>(STMP, Wid2 + (size_t)(i+1)*E*E,
                                    nullptr, nullptr, RSING, RSING, NA, 128, 0);
    }

    // final molecule reduction
    cudaMemsetAsync(out, 0, (size_t)NM*E*sizeof(float));
    final_kernel<<<512, 256>>>(ROUT, RSING, bseg, cmp, csg, out);
}

// round 7
// speedup vs baseline: 1.6452x; 1.6452x over previous
#include <cuda_runtime.h>
#include <cuda_bf16.h>
#include <cstdint>
#include <cstddef>
#include <math.h>

// ---------------- problem constants ----------------
constexpr int EG  = 300000;   // edges
constexpr int TT  = 1000000;  // triplets
constexpr int NA  = 20000;    // atoms
constexpr int NM  = 1000;     // molecules
constexpr int E   = 128;      // embedding
constexpr int NR  = 6;
constexpr int NABF= 7;
constexpr int NB  = 3;

// ---------------- scratch layout (floats) ----------------
constexpr size_t OFF_RBF  = 0;                                   // EG*6
constexpr size_t OFF_CAT  = OFF_RBF  + (size_t)EG*6;             // EG*384
constexpr size_t OFF_X    = OFF_CAT  + (size_t)EG*384;           // EG*128
constexpr size_t OFF_XKJ  = OFF_X    + (size_t)EG*128;
constexpr size_t OFF_AGGR = OFF_XKJ  + (size_t)EG*128;
constexpr size_t OFF_PA   = OFF_AGGR + (size_t)EG*128;           // NA*128
constexpr size_t OFF_HAT  = OFF_PA   + (size_t)NA*128;
constexpr size_t OFF_ROUT = OFF_HAT  + (size_t)NA*128;
constexpr size_t OFF_RSING= OFF_ROUT + (size_t)NA*128;
constexpr size_t OFF_STMP = OFF_RSING+ (size_t)NA*128;
constexpr size_t OFF_X0   = OFF_STMP + (size_t)NA*128;
constexpr size_t OFF_WT   = OFF_X0   + (size_t)NA*128;
// inside WT (float granules; bf16 arrays occupy half of each slot)
constexpr size_t WT_EMB_H = 0;         // 384*128 bf16 elems
constexpr size_t WT_EMB_L = 49152;
constexpr size_t WT_O1_H  = 98304;     // 4*128*128 bf16 elems per slot
constexpr size_t WT_O1_L  = 163840;
constexpr size_t WT_OUT_H = 229376;
constexpr size_t WT_OUT_L = 294912;
constexpr size_t WT_ID1_H = 360448;
constexpr size_t WT_ID1_L = 425984;
constexpr size_t WT_ID2_H = 491520;
constexpr size_t WT_ID2_L = 557056;
constexpr size_t WT_JI_H  = 622592;    // 3*128*128
constexpr size_t WT_JI_L  = 671744;
constexpr size_t WT_KJ_H  = 720896;
constexpr size_t WT_KJ_L  = 770048;
constexpr size_t WT_RES_H = 819200;
constexpr size_t WT_RES_L = 868352;
constexpr size_t WT_TOTAL = 917504;
constexpr size_t TOTAL_F  = OFF_WT + WT_TOTAL;

__device__ float g_buf[TOTAL_F];

// ---------------- helpers ----------------
__device__ __forceinline__ float silu_f(float x) { return x / (1.f + __expf(-x)); }

#define MMA_BF16(d, a, b0, b1) \
    asm volatile("mma.sync.aligned.m16n8k16.row.col.f32.bf16.bf16.f32 " \
        "{%0,%1,%2,%3},{%4,%5,%6,%7},{%8,%9},{%0,%1,%2,%3};" \
        : "+f"((d)[0]), "+f"((d)[1]), "+f"((d)[2]), "+f"((d)[3]) \
        : "r"((a)[0]), "r"((a)[1]), "r"((a)[2]), "r"((a)[3]), "r"(b0), "r"(b1))

#define RED4(ptr, a, b, c, dd) \
    asm volatile("red.global.add.v4.f32 [%0], {%1,%2,%3,%4};" \
        :: "l"(ptr), "f"(a), "f"(b), "f"(c), "f"(dd) : "memory")
#define RED2(ptr, a, b) \
    asm volatile("red.global.add.v2.f32 [%0], {%1,%2};" \
        :: "l"(ptr), "f"(a), "f"(b) : "memory")

__device__ __forceinline__ uint32_t pack_bf16_hi(float a, float b, float& la, float& lb) {
    __nv_bfloat162 h = __floats2bfloat162_rn(a, b);   // x=a (low), y=b (high)
    la = a - __bfloat162float(h.x);
    lb = b - __bfloat162float(h.y);
    return *(uint32_t*)&h;
}
__device__ __forceinline__ uint32_t pack_bf16(float a, float b) {
    __nv_bfloat162 h = __floats2bfloat162_rn(a, b);
    return *(uint32_t*)&h;
}

// ---------------- dynamic smem layout (bytes after 1024-align) ----------------
// padded rows: 64 bf16 data + 8 pad = 72 bf16 = 144 bytes per row, 128 rows
constexpr int STRB   = 144;
constexpr int TILEB  = 128 * STRB;   // 18432
constexpr int SM_AH   = 0;
constexpr int SM_AL   = SM_AH + TILEB;
constexpr int SM_BH   = SM_AL + TILEB;
constexpr int SM_BL   = SM_BH + TILEB;       // ends 73728
constexpr int SM_WMUL = 73728;   // 6*128*4
constexpr int SM_WSC  = 76800;
constexpr int SM_RBF6 = 79872;   // 128*6*4
constexpr int SM_BIAS = 82944;   // 128*4
constexpr int SM_END  = 83456;
constexpr int SMEM_DYN = SM_END + 1024 + 128;

// ---------------- basis kernels ----------------
__global__ void rbf_kernel(const float* __restrict__ R,
                           const int* __restrict__ idx_i,
                           const int* __restrict__ idx_j,
                           float* __restrict__ rbf)
{
    const float PI_F = 3.14159265358979323846f;
    const float c = sqrtf(2.f / 5.f);
    for (int e = blockIdx.x * blockDim.x + threadIdx.x; e < EG;
         e += gridDim.x * blockDim.x) {
        int i = idx_i[e], j = idx_j[e];
        float dx = R[3*i+0] - R[3*j+0];
        float dy = R[3*i+1] - R[3*j+1];
        float dz = R[3*i+2] - R[3*j+2];
        float d = sqrtf(dx*dx + dy*dy + dz*dz);
        d = fmaxf(d, 1e-2f);
        float inv = 1.f / d;
        float arg = d * (PI_F / 5.f);
        #pragma unroll
        for (int r = 0; r < NR; r++)
            rbf[(size_t)e*NR + r] = c * sinf((float)(r+1) * arg) * inv;
    }
}

__global__ void x0_kernel(const int* __restrict__ Z,
                          const float* __restrict__ emb,
                          float* __restrict__ x0)
{
    size_t total = (size_t)NA * E;
    for (size_t idx = blockIdx.x * (size_t)blockDim.x + threadIdx.x; idx < total;
         idx += (size_t)gridDim.x * blockDim.x) {
        int a = (int)(idx >> 7);
        int c = (int)(idx & 127);
        x0[idx] = emb[(size_t)Z[a]*E + c];
    }
}

// R1-proven: build [x0_i | x0_j | silu(rbf@W_rbf_emb)]
__global__ __launch_bounds__(128) void buildcat_kernel(
    const int* __restrict__ Z,
    const int* __restrict__ idx_i,
    const int* __restrict__ idx_j,
    const float* __restrict__ emb,
    const float* __restrict__ Wrbf,       // [6,128]
    const float* __restrict__ rbf,
    float* __restrict__ cat)
{
    __shared__ float ws[NR*E];
    for (int k = threadIdx.x; k < NR*E; k += 128) ws[k] = Wrbf[k];
    __syncthreads();
    int t = threadIdx.x;
    for (int e = blockIdx.x; e < EG; e += gridDim.x) {
        int ai = idx_i[e], aj = idx_j[e];
        float s = 0.f;
        #pragma unroll
        for (int r = 0; r < NR; r++)
            s += rbf[(size_t)e*NR + r] * ws[r*E + t];
        s = silu_f(s);
        size_t base = (size_t)e * 384;
        cat[base + t]       = emb[(size_t)Z[ai]*E + t];
        cat[base + 128 + t] = emb[(size_t)Z[aj]*E + t];
        cat[base + 256 + t] = s;
    }
}

// transpose + bf16-split: src[b][k][128] -> dh/dl[b][n][K] (bf16)
__global__ void tsplit_kernel(const float* __restrict__ src,
                              __nv_bfloat16* __restrict__ dh,
                              __nv_bfloat16* __restrict__ dl, int K)
{
    int b = blockIdx.y;
    size_t tot = (size_t)K * 128;
    const float* s = src + (size_t)b * tot;
    __nv_bfloat16* h = dh + (size_t)b * tot;
    __nv_bfloat16* l = dl + (size_t)b * tot;
    for (size_t idx = blockIdx.x * (size_t)blockDim.x + threadIdx.x; idx < tot;
         idx += (size_t)gridDim.x * blockDim.x) {
        int k = (int)(idx >> 7), n = (int)(idx & 127);
        float v = s[idx];
        __nv_bfloat16 hi = __float2bfloat16(v);
        float lo = v - __bfloat162float(hi);
        h[(size_t)n*K + k] = hi;
        l[(size_t)n*K + k] = __float2bfloat16(lo);
    }
}

// ---------------- mma.sync bf16x3 GEMM: C[M,128] = epi(A[M,K] @ W[K,128]) ----------------
// explicit per-thread LDS fragment loads (no ldmatrix, no swizzle)
__global__ __launch_bounds__(256) void gemm_mma(
    const float* __restrict__ A,
    const __nv_bfloat16* __restrict__ Bh,
    const __nv_bfloat16* __restrict__ Bl,           // [128 n][K] bf16
    const float* __restrict__ bias,
    const float* __restrict__ mulW,                 // [6,128]: v *= rbf@mulW
    const float* __restrict__ addp,
    const float* __restrict__ scW,                  // [6,128]: red (rbf@scW)*v -> sc_out[sc_idx]
    const int* __restrict__ sc_idx, float* __restrict__ sc_out,
    const float* __restrict__ rbf,                  // [M,6]
    float* __restrict__ C,
    int M, int K, int act)
{
    extern __shared__ char smraw[];
    char* sm = (char*)(((uintptr_t)smraw + 1023) & ~(uintptr_t)1023);
    float* wmul_s = (float*)(sm + SM_WMUL);
    float* wsc_s  = (float*)(sm + SM_WSC);
    float* rbf6   = (float*)(sm + SM_RBF6);
    float* bias_s = (float*)(sm + SM_BIAS);

    int tid = threadIdx.x;
    int lane = tid & 31;
    int wid = tid >> 5;
    int bm = blockIdx.x * 128;
    int need_rbf = (mulW != nullptr) || (scW != nullptr);

    // prologue
    for (int k = tid; k < NR*E; k += 256) {
        if (mulW) wmul_s[k] = mulW[k];
        if (scW)  wsc_s[k]  = scW[k];
    }
    for (int k = tid; k < E; k += 256) bias_s[k] = bias ? bias[k] : 0.f;
    if (need_rbf && tid < 128) {
        int g = bm + tid; if (g >= M) g = M - 1;
        #pragma unroll
        for (int q = 0; q < NR; q++) rbf6[tid*NR + q] = rbf[(size_t)g*NR + q];
    }
    __syncthreads();

    // warp tiling: 4 m-warps x 2 n-warps; warp tile 32m x 64n
    int wm = (wid & 3) * 32;
    int wn = (wid >> 2) * 64;
    int lq = lane >> 2;        // groupID (0..7)
    int lr4 = lane & 3;        // threadID_in_group

    float acc[2][8][4];
    #pragma unroll
    for (int a0 = 0; a0 < 2; a0++)
        #pragma unroll
        for (int b0 = 0; b0 < 8; b0++)
            #pragma unroll
            for (int c0 = 0; c0 < 4; c0++) acc[a0][b0][c0] = 0.f;

    // per-thread fragment base addresses (byte offsets in padded layout)
    const char* Abase = sm + SM_AH + (wm + lq) * STRB + lr4 * 4;
    const char* Bbase = sm + SM_BH + (wn + lq) * STRB + lr4 * 4;

    int nch = K >> 6;   // K-chunks of 64
    for (int c = 0; c < nch; c++) {
        int kc = c << 6;

        // ---- produce B tiles (pre-split bf16 global -> padded smem) ----
        #pragma unroll
        for (int u = 0; u < 8; u++) {
            int f = u*256 + tid;           // 0..2047
            int which = f >> 10;           // 0:hi 1:lo
            int g2 = f & 1023;
            int n = g2 >> 3, ch = g2 & 7;
            const __nv_bfloat16* src = which ? Bl : Bh;
            uint4 val = *(const uint4*)&src[(size_t)n*K + kc + ch*8];
            char* dst = sm + (which ? SM_BL : SM_BH);
            *(uint4*)(dst + n*STRB + ch*16) = val;
        }
        // ---- produce A tiles (fp32 -> bf16 hi/lo) ----
        #pragma unroll
        for (int u = 0; u < 4; u++) {
            int f = u*256 + tid;           // 0..1023
            int rr = f >> 3, ch = f & 7;
            int g = bm + rr;
            int k = kc + ch*8;
            float v[8];
            if (g < M) {
                float4 p0 = *(const float4*)&A[(size_t)g*K + k];
                float4 p1 = *(const float4*)&A[(size_t)g*K + k + 4];
                v[0]=p0.x; v[1]=p0.y; v[2]=p0.z; v[3]=p0.w;
                v[4]=p1.x; v[5]=p1.y; v[6]=p1.z; v[7]=p1.w;
            } else {
                #pragma unroll
                for (int e2 = 0; e2 < 8; e2++) v[e2] = 0.f;
            }
            uint4 hb, lb;
            float l0, l1;
            hb.x = pack_bf16_hi(v[0], v[1], l0, l1); lb.x = pack_bf16(l0, l1);
            hb.y = pack_bf16_hi(v[2], v[3], l0, l1); lb.y = pack_bf16(l0, l1);
            hb.z = pack_bf16_hi(v[4], v[5], l0, l1); lb.z = pack_bf16(l0, l1);
            hb.w = pack_bf16_hi(v[6], v[7], l0, l1); lb.w = pack_bf16(l0, l1);
            *(uint4*)(sm + SM_AH + rr*STRB + ch*16) = hb;
            *(uint4*)(sm + SM_AL + rr*STRB + ch*16) = lb;
        }
        __syncthreads();

        // ---- consume: explicit fragment loads + mma ----
        #pragma unroll
        for (int ks = 0; ks < 4; ks++) {
            uint32_t ah[2][4], al[2][4];
            #pragma unroll
            for (int mt = 0; mt < 2; mt++) {
                const char* pA = Abase + mt*(16*STRB) + ks*32;
                ah[mt][0] = *(const uint32_t*)(pA);
                ah[mt][1] = *(const uint32_t*)(pA + 8*STRB);
                ah[mt][2] = *(const uint32_t*)(pA + 16);
                ah[mt][3] = *(const uint32_t*)(pA + 8*STRB + 16);
                const char* pL = pA + TILEB;   // SM_AL
                al[mt][0] = *(const uint32_t*)(pL);
                al[mt][1] = *(const uint32_t*)(pL + 8*STRB);
                al[mt][2] = *(const uint32_t*)(pL + 16);
                al[mt][3] = *(const uint32_t*)(pL + 8*STRB + 16);
            }
            #pragma unroll
            for (int nt = 0; nt < 8; nt++) {
                const char* pB = Bbase + nt*(8*STRB) + ks*32;
                uint32_t b0h = *(const uint32_t*)(pB);
                uint32_t b1h = *(const uint32_t*)(pB + 16);
                uint32_t b0l = *(const uint32_t*)(pB + TILEB);
                uint32_t b1l = *(const uint32_t*)(pB + TILEB + 16);
                #pragma unroll
                for (int mt = 0; mt < 2; mt++) {
                    MMA_BF16(acc[mt][nt], ah[mt], b0h, b1h);
                    MMA_BF16(acc[mt][nt], ah[mt], b0l, b1l);
                    MMA_BF16(acc[mt][nt], al[mt], b0h, b1h);
                }
            }
        }
        __syncthreads();
    }

    // ---- epilogue (C frag: c0,c1 = (row=g, col=2t,2t+1); c2,c3 = row+8) ----
    #pragma unroll
    for (int mt = 0; mt < 2; mt++) {
        int lrbase = wm + mt*16 + lq;
        #pragma unroll
        for (int h = 0; h < 2; h++) {
            int lrow = lrbase + h*8;
            int row = bm + lrow;
            if (row >= M) continue;
            int asc = scW ? sc_idx[row] : 0;
            #pragma unroll
            for (int nt = 0; nt < 8; nt++) {
                int col = wn + nt*8 + lr4*2;
                float v0 = acc[mt][nt][2*h+0] + bias_s[col];
                float v1 = acc[mt][nt][2*h+1] + bias_s[col+1];
                if (act) { v0 = silu_f(v0); v1 = silu_f(v1); }
                if (mulW) {
                    float d0 = 0.f, d1 = 0.f;
                    #pragma unroll
                    for (int q = 0; q < NR; q++) {
                        float rq = rbf6[lrow*NR + q];
                        d0 += rq * wmul_s[q*E + col];
                        d1 += rq * wmul_s[q*E + col + 1];
                    }
                    v0 *= d0; v1 *= d1;
                }
                if (addp) {
                    float2 av = *(const float2*)&addp[(size_t)row*128 + col];
                    v0 += av.x; v1 += av.y;
                }
                *(float2*)&C[(size_t)row*128 + col] = make_float2(v0, v1);
                if (scW) {
                    float g0 = 0.f, g1 = 0.f;
                    #pragma unroll
                    for (int q = 0; q < NR; q++) {
                        float rq = rbf6[lrow*NR + q];
                        g0 += rq * wsc_s[q*E + col];
                        g1 += rq * wsc_s[q*E + col + 1];
                    }
                    RED2(&sc_out[(size_t)asc*128 + col], g0*v0, g1*v1);
                }
            }
        }
    }
}

// ---------------- triplet messages + scatter to edges ----------------
__global__ __launch_bounds__(256) void triplet_kernel(
    const float* __restrict__ xkj,
    const float* __restrict__ cosik,
    const int* __restrict__ idx_kj,
    const int* __restrict__ idx_ji,
    const float* __restrict__ Wabf,       // [7,128]
    float* __restrict__ aggr)
{
    __shared__ float ws[NABF*E];
    for (int k = threadIdx.x; k < NABF*E; k += 256) ws[k] = Wabf[k];
    __syncthreads();
    int lane = threadIdx.x & 31;
    int warp = (blockIdx.x * 256 + threadIdx.x) >> 5;
    int nwarps = (gridDim.x * 256) >> 5;
    int c = lane << 2;
    for (int t = warp; t < TT; t += nwarps) {
        int ekj = idx_kj[t];
        int eji = idx_ji[t];
        float x = fminf(1.f, fmaxf(-1.f, cosik[t]));
        // cos(k*acos(x)) = T_k(x), Chebyshev recurrence (exact identity)
        float a0 = 1.f, a1 = x;
        float a2 = 2.f*x*a1 - a0;
        float a3 = 2.f*x*a2 - a1;
        float a4 = 2.f*x*a3 - a2;
        float a5 = 2.f*x*a4 - a3;
        float a6 = 2.f*x*a5 - a4;
        float4 xv = *(const float4*)&xkj[(size_t)ekj*128 + c];
        float m[4];
        #pragma unroll
        for (int j = 0; j < 4; j++) {
            int cc = c + j;
            m[j] = a0*ws[cc] + a1*ws[E+cc] + a2*ws[2*E+cc] + a3*ws[3*E+cc]
                 + a4*ws[4*E+cc] + a5*ws[5*E+cc] + a6*ws[6*E+cc];
        }
        RED4(&aggr[(size_t)eji*128 + c], xv.x*m[0], xv.y*m[1], xv.z*m[2], xv.w*m[3]);
    }
}

// ---------------- final molecule reduction ----------------
__global__ void final_kernel(const float* __restrict__ ro,
                             const float* __restrict__ rs,
                             const int* __restrict__ bseg,
                             const float* __restrict__ cmp_p,
                             const float* __restrict__ csg_p,
                             float* __restrict__ out)
{
    float cmp = cmp_p[0], csg = csg_p[0];
    size_t total = (size_t)NA * 32;
    for (size_t idx = blockIdx.x * (size_t)blockDim.x + threadIdx.x; idx < total;
         idx += (size_t)gridDim.x * blockDim.x) {
        int a = (int)(idx >> 5);
        int c = (int)(idx & 31) << 2;
        int m = bseg[a];
        float4 o = *(const float4*)&ro[(size_t)a*128 + c];
        float4 s = *(const float4*)&rs[(size_t)a*128 + c];
        RED4(&out[(size_t)m*128 + c],
             cmp*o.x + csg*s.x, cmp*o.y + csg*s.y,
             cmp*o.z + csg*s.z, cmp*o.w + csg*s.w);
    }
}

// ---------------- host orchestration ----------------
extern "C" void kernel_launch(void* const* d_in, const int* in_sizes, int n_in,
                              void* d_out, int out_size)
{
    const int*   Z      = (const int*)  d_in[0];
    const float* R      = (const float*)d_in[1];
    const int*   bseg   = (const int*)  d_in[2];
    const int*   idx_i  = (const int*)  d_in[3];
    const int*   idx_j  = (const int*)  d_in[4];
    const int*   idx_kj = (const int*)  d_in[5];
    const int*   idx_ji = (const int*)  d_in[6];
    const float* cosik  = (const float*)d_in[7];
    const float* emb    = (const float*)d_in[8];
    const float* Wrbf   = (const float*)d_in[9];
    const float* Wemb   = (const float*)d_in[10];
    const float* bemb   = (const float*)d_in[11];
    const float* Worbf  = (const float*)d_in[12];
    const float* Wo1    = (const float*)d_in[13];
    const float* bo1    = (const float*)d_in[14];
    const float* Wout   = (const float*)d_in[15];
    const float* Wid1   = (const float*)d_in[16];
    const float* bid1   = (const float*)d_in[17];
    const float* Wid2   = (const float*)d_in[18];
    const float* Wji    = (const float*)d_in[19];
    const float* bji    = (const float*)d_in[20];
    const float* Wkj    = (const float*)d_in[21];
    const float* bkj    = (const float*)d_in[22];
    const float* Wirbf  = (const float*)d_in[23];
    const float* Wabf   = (const float*)d_in[24];
    const float* Wres   = (const float*)d_in[25];
    const float* bres   = (const float*)d_in[26];
    const float* cmp    = (const float*)d_in[27];
    const float* csg    = (const float*)d_in[28];
    float* out = (float*)d_out;

    cudaFuncSetAttribute(gemm_mma, cudaFuncAttributeMaxDynamicSharedMemorySize, SMEM_DYN);

    float* buf = nullptr;
    cudaGetSymbolAddress((void**)&buf, g_buf);
    float* RBF   = buf + OFF_RBF;
    float* CAT   = buf + OFF_CAT;
    float* X     = buf + OFF_X;
    float* XKJ   = buf + OFF_XKJ;
    float* AGGR  = buf + OFF_AGGR;
    float* PA    = buf + OFF_PA;
    float* HAT   = buf + OFF_HAT;
    float* ROUT  = buf + OFF_ROUT;
    float* RSING = buf + OFF_RSING;
    float* STMP  = buf + OFF_STMP;
    float* X0    = buf + OFF_X0;
    float* WT    = buf + OFF_WT;

    #define BF(off) ((__nv_bfloat16*)(WT + (off)))

    const int GE = (EG + 127) / 128;   // 2344
    const int GA = (NA + 127) / 128;   // 157

    // ---- prep ----
    rbf_kernel<<<1024, 256>>>(R, idx_i, idx_j, RBF);
    x0_kernel<<<1024, 256>>>(Z, emb, X0);
    buildcat_kernel<<<4096, 128>>>(Z, idx_i, idx_j, emb, Wrbf, RBF, CAT);
    {
        dim3 g4(48, 4), g3(48, 3);
        tsplit_kernel<<<dim3(96,1), 256>>>(Wemb, BF(WT_EMB_H), BF(WT_EMB_L), 384);
        tsplit_kernel<<<g4, 256>>>(Wo1,  BF(WT_O1_H),  BF(WT_O1_L),  128);
        tsplit_kernel<<<g4, 256>>>(Wout, BF(WT_OUT_H), BF(WT_OUT_L), 128);
        tsplit_kernel<<<g4, 256>>>(Wid1, BF(WT_ID1_H), BF(WT_ID1_L), 128);
        tsplit_kernel<<<g4, 256>>>(Wid2, BF(WT_ID2_H), BF(WT_ID2_L), 128);
        tsplit_kernel<<<g3, 256>>>(Wji,  BF(WT_JI_H),  BF(WT_JI_L),  128);
        tsplit_kernel<<<g3, 256>>>(Wkj,  BF(WT_KJ_H),  BF(WT_KJ_L),  128);
        tsplit_kernel<<<g3, 256>>>(Wres, BF(WT_RES_H), BF(WT_RES_L), 128);
    }

    // ---- embedding block (+fused output-block-0 scatter) ----
    cudaMemsetAsync(PA, 0, (size_t)NA*E*sizeof(float));
    gemm_mma<<<GE, 256, SMEM_DYN>>>(CAT, BF(WT_EMB_H), BF(WT_EMB_L), bemb,
                                    nullptr, nullptr,
                                    Worbf, idx_i, PA, RBF,
                                    X, EG, 384, 1);
    gemm_mma<<<GA, 256, SMEM_DYN>>>(PA, BF(WT_O1_H), BF(WT_O1_L), bo1,
                                    nullptr, nullptr, nullptr, nullptr, nullptr, nullptr,
                                    HAT, NA, 128, 1);
    gemm_mma<<<GA, 256, SMEM_DYN>>>(HAT, BF(WT_OUT_H), BF(WT_OUT_L), nullptr,
                                    nullptr, nullptr, nullptr, nullptr, nullptr, nullptr,
                                    ROUT, NA, 128, 0);
    gemm_mma<<<GA, 256, SMEM_DYN>>>(X0, BF(WT_ID1_H), BF(WT_ID1_L), bid1,
                                    nullptr, nullptr, nullptr, nullptr, nullptr, nullptr,
                                    STMP, NA, 128, 1);
    gemm_mma<<<GA, 256, SMEM_DYN>>>(STMP, BF(WT_ID2_H), BF(WT_ID2_L), nullptr,
                                    nullptr, nullptr, nullptr, nullptr, nullptr, nullptr,
                                    RSING, NA, 128, 0);

    for (int i = 0; i < NB; i++) {
        size_t wo = (size_t)i * 128 * 128;          // bf16 ELEMENT offset
        // x_ji -> AGGR (triplet messages accumulate on top)
        gemm_mma<<<GE, 256, SMEM_DYN>>>(X, BF(WT_JI_H) + wo, BF(WT_JI_L) + wo, bji + (size_t)i*E,
                                        nullptr, nullptr, nullptr, nullptr, nullptr, nullptr,
                                        AGGR, EG, 128, 1);
        // x_kj = silu(x@Wkj+b) * (rbf@Wirbf)
        gemm_mma<<<GE, 256, SMEM_DYN>>>(X, BF(WT_KJ_H) + wo, BF(WT_KJ_L) + wo, bkj + (size_t)i*E,
                                        Wirbf + (size_t)i*NR*E, nullptr,
                                        nullptr, nullptr, nullptr, RBF,
                                        XKJ, EG, 128, 1);
        triplet_kernel<<<2048, 256>>>(XKJ, cosik, idx_kj, idx_ji,
                                      Wabf + (size_t)i*NABF*E, AGGR);
        cudaMemsetAsync(PA, 0, (size_t)NA*E*sizeof(float));
        // x = h + silu(h@Wres+b); fused output-block(i+1) scatter -> PA
        gemm_mma<<<GE, 256, SMEM_DYN>>>(AGGR, BF(WT_RES_H) + wo, BF(WT_RES_L) + wo, bres + (size_t)i*E,
                                        nullptr, AGGR,
                                        Worbf + (size_t)(i+1)*NR*E, idx_i, PA, RBF,
                                        X, EG, 128, 1);
        size_t wo1 = (size_t)(i+1) * 128 * 128;     // bf16 ELEMENT offset
        gemm_mma<<<GA, 256, SMEM_DYN>>>(PA, BF(WT_O1_H) + wo1, BF(WT_O1_L) + wo1, bo1 + (size_t)(i+1)*E,
                                        nullptr, nullptr, nullptr, nullptr, nullptr, nullptr,
                                        HAT, NA, 128, 1);
        gemm_mma<<<GA, 256, SMEM_DYN>>>(HAT, BF(WT_OUT_H) + wo1, BF(WT_OUT_L) + wo1, nullptr,
                                        nullptr, ROUT, nullptr, nullptr, nullptr, nullptr,
                                        ROUT, NA, 128, 0);
        gemm_mma<<<GA, 256, SMEM_DYN>>>(RSING, BF(WT_ID1_H) + wo1, BF(WT_ID1_L) + wo1, bid1 + (size_t)(i+1)*E,
                                        nullptr, nullptr, nullptr, nullptr, nullptr, nullptr,
                                        STMP, NA, 128, 1);
        gemm_mma<<<GA, 256, SMEM_DYN>>>(STMP, BF(WT_ID2_H) + wo1, BF(WT_ID2_L) + wo1, nullptr,
                                        nullptr, RSING, nullptr, nullptr, nullptr, nullptr,
                                        RSING, NA, 128, 0);
    }

    cudaMemsetAsync(out, 0, (size_t)NM*E*sizeof(float));
    final_kernel<<<512, 256>>>(ROUT, RSING, bseg, cmp, csg, out);
}

// round 8
// speedup vs baseline: 1.6488x; 1.0022x over previous
#include <cuda_runtime.h>
#include <cuda_bf16.h>
#include <cstdint>
#include <cstddef>
#include <math.h>

// ---------------- problem constants ----------------
constexpr int EG  = 300000;   // edges
constexpr int TT  = 1000000;  // triplets
constexpr int NA  = 20000;    // atoms
constexpr int NM  = 1000;     // molecules
constexpr int E   = 128;      // embedding
constexpr int NR  = 6;
constexpr int NABF= 7;
constexpr int NB  = 3;

// ---------------- scratch layout (float granules) ----------------
constexpr size_t OFF_RBF  = 0;                                    // EG*6 f32
constexpr size_t OFF_CATH = OFF_RBF  + (size_t)EG*6;              // bf16[EG][384]
constexpr size_t OFF_CATL = OFF_CATH + (size_t)EG*192;
constexpr size_t OFF_XH   = OFF_CATL + (size_t)EG*192;            // bf16[EG][128]
constexpr size_t OFF_XL   = OFF_XH   + (size_t)EG*64;
constexpr size_t OFF_XKJ  = OFF_XL   + (size_t)EG*64;             // f32[EG][128]
constexpr size_t OFF_AGGR = OFF_XKJ  + (size_t)EG*128;
constexpr size_t OFF_PA   = OFF_AGGR + (size_t)EG*128;            // f32[NA][128]
constexpr size_t OFF_HAT  = OFF_PA   + (size_t)NA*128;
constexpr size_t OFF_ROUT = OFF_HAT  + (size_t)NA*128;
constexpr size_t OFF_RSING= OFF_ROUT + (size_t)NA*128;
constexpr size_t OFF_STMP = OFF_RSING+ (size_t)NA*128;
constexpr size_t OFF_X0   = OFF_STMP + (size_t)NA*128;
constexpr size_t OFF_WT   = OFF_X0   + (size_t)NA*128;
// inside WT (bf16 element offsets relative to BF(base))
constexpr size_t WT_EMB_H = 0;         // 384*128
constexpr size_t WT_EMB_L = 49152;
constexpr size_t WT_O1_H  = 98304;     // 4*128*128 per slot
constexpr size_t WT_O1_L  = 163840;
constexpr size_t WT_OUT_H = 229376;
constexpr size_t WT_OUT_L = 294912;
constexpr size_t WT_ID1_H = 360448;
constexpr size_t WT_ID1_L = 425984;
constexpr size_t WT_ID2_H = 491520;
constexpr size_t WT_ID2_L = 557056;
constexpr size_t WT_JI_H  = 622592;    // 3*128*128
constexpr size_t WT_JI_L  = 671744;
constexpr size_t WT_KJ_H  = 720896;
constexpr size_t WT_KJ_L  = 770048;
constexpr size_t WT_RES_H = 819200;
constexpr size_t WT_RES_L = 868352;
constexpr size_t WT_TOTAL = 917504;
constexpr size_t TOTAL_F  = OFF_WT + WT_TOTAL;

__device__ float g_buf[TOTAL_F];

// ---------------- helpers ----------------
__device__ __forceinline__ uint32_t smem_u32(const void* p) {
    uint32_t a;
    asm("{ .reg .u64 t; cvta.to.shared.u64 t, %1; cvt.u32.u64 %0, t; }" : "=r"(a) : "l"(p));
    return a;
}
__device__ __forceinline__ float silu_f(float x) { return x / (1.f + __expf(-x)); }

#define LDSM4(rr, addr) \
    asm volatile("ldmatrix.sync.aligned.m8n8.x4.shared.b16 {%0,%1,%2,%3}, [%4];" \
        : "=r"((rr)[0]), "=r"((rr)[1]), "=r"((rr)[2]), "=r"((rr)[3]) : "r"(addr))

#define MMA_BF16(d, a, b0, b1) \
    asm volatile("mma.sync.aligned.m16n8k16.row.col.f32.bf16.bf16.f32 " \
        "{%0,%1,%2,%3},{%4,%5,%6,%7},{%8,%9},{%0,%1,%2,%3};" \
        : "+f"((d)[0]), "+f"((d)[1]), "+f"((d)[2]), "+f"((d)[3]) \
        : "r"((a)[0]), "r"((a)[1]), "r"((a)[2]), "r"((a)[3]), "r"(b0), "r"(b1))

#define CP_ASYNC16(dst, src) \
    asm volatile("cp.async.cg.shared.global [%0], [%1], 16;" :: "r"(dst), "l"(src) : "memory")
#define CP_COMMIT() asm volatile("cp.async.commit_group;" ::: "memory")
#define CP_WAIT0()  asm volatile("cp.async.wait_group 0;" ::: "memory")

#define RED4(ptr, a, b, c, dd) \
    asm volatile("red.global.add.v4.f32 [%0], {%1,%2,%3,%4};" \
        :: "l"(ptr), "f"(a), "f"(b), "f"(c), "f"(dd) : "memory")
#define RED2(ptr, a, b) \
    asm volatile("red.global.add.v2.f32 [%0], {%1,%2};" \
        :: "l"(ptr), "f"(a), "f"(b) : "memory")

__device__ __forceinline__ uint32_t pack_bf16_hi(float a, float b, float& la, float& lb) {
    __nv_bfloat162 h = __floats2bfloat162_rn(a, b);   // x=a (low), y=b (high)
    la = a - __bfloat162float(h.x);
    lb = b - __bfloat162float(h.y);
    return *(uint32_t*)&h;
}
__device__ __forceinline__ uint32_t pack_bf16(float a, float b) {
    __nv_bfloat162 h = __floats2bfloat162_rn(a, b);
    return *(uint32_t*)&h;
}

// ---------------- smem layout (bytes after 1024-align) ----------------
// swizzled tiles: 128 rows x 128B (64 bf16); byte = row*128 + ((ch ^ (row&7))<<4)
constexpr int TILE  = 16384;
constexpr int SM_AH   = 0;
constexpr int SM_AL   = SM_AH + TILE;
constexpr int SM_BH   = SM_AL + TILE;
constexpr int SM_BL   = SM_BH + TILE;      // ends 65536
constexpr int SM_WMUL = 65536;   // 6*128*4
constexpr int SM_WSC  = 68608;
constexpr int SM_RBF6 = 71680;   // 128*6*4
constexpr int SM_BIAS = 74752;   // 128*4
constexpr int SM_END  = 75264;
constexpr int SMEM_DYN = SM_END + 1024 + 128;

// ---------------- basis kernels ----------------
__global__ void rbf_kernel(const float* __restrict__ R,
                           const int* __restrict__ idx_i,
                           const int* __restrict__ idx_j,
                           float* __restrict__ rbf)
{
    const float PI_F = 3.14159265358979323846f;
    const float c = sqrtf(2.f / 5.f);
    for (int e = blockIdx.x * blockDim.x + threadIdx.x; e < EG;
         e += gridDim.x * blockDim.x) {
        int i = idx_i[e], j = idx_j[e];
        float dx = R[3*i+0] - R[3*j+0];
        float dy = R[3*i+1] - R[3*j+1];
        float dz = R[3*i+2] - R[3*j+2];
        float d = sqrtf(dx*dx + dy*dy + dz*dz);
        d = fmaxf(d, 1e-2f);
        float inv = 1.f / d;
        float arg = d * (PI_F / 5.f);
        #pragma unroll
        for (int r = 0; r < NR; r++)
            rbf[(size_t)e*NR + r] = c * sinf((float)(r+1) * arg) * inv;
    }
}

__global__ void x0_kernel(const int* __restrict__ Z,
                          const float* __restrict__ emb,
                          float* __restrict__ x0)
{
    size_t total = (size_t)NA * E;
    for (size_t idx = blockIdx.x * (size_t)blockDim.x + threadIdx.x; idx < total;
         idx += (size_t)gridDim.x * blockDim.x) {
        int a = (int)(idx >> 7);
        int c = (int)(idx & 127);
        x0[idx] = emb[(size_t)Z[a]*E + c];
    }
}

// build [x0_i | x0_j | silu(rbf@W_rbf_emb)] pre-split to bf16 hi/lo
__global__ __launch_bounds__(128) void buildcat_kernel(
    const int* __restrict__ Z,
    const int* __restrict__ idx_i,
    const int* __restrict__ idx_j,
    const float* __restrict__ emb,
    const float* __restrict__ Wrbf,       // [6,128]
    const float* __restrict__ rbf,
    __nv_bfloat16* __restrict__ ch_,
    __nv_bfloat16* __restrict__ cl_)
{
    __shared__ float ws[NR*E];
    for (int k = threadIdx.x; k < NR*E; k += 128) ws[k] = Wrbf[k];
    __syncthreads();
    int t = threadIdx.x;
    for (int e = blockIdx.x; e < EG; e += gridDim.x) {
        int ai = idx_i[e], aj = idx_j[e];
        float s = 0.f;
        #pragma unroll
        for (int r = 0; r < NR; r++)
            s += rbf[(size_t)e*NR + r] * ws[r*E + t];
        s = silu_f(s);
        float vi = emb[(size_t)Z[ai]*E + t];
        float vj = emb[(size_t)Z[aj]*E + t];
        size_t base = (size_t)e * 384;
        __nv_bfloat16 h;
        h = __float2bfloat16(vi); ch_[base + t] = h;
        cl_[base + t] = __float2bfloat16(vi - __bfloat162float(h));
        h = __float2bfloat16(vj); ch_[base + 128 + t] = h;
        cl_[base + 128 + t] = __float2bfloat16(vj - __bfloat162float(h));
        h = __float2bfloat16(s);  ch_[base + 256 + t] = h;
        cl_[base + 256 + t] = __float2bfloat16(s - __bfloat162float(h));
    }
}

// transpose + bf16-split: src[b][k][128] -> dh/dl[b][n][K] (bf16)
__global__ void tsplit_kernel(const float* __restrict__ src,
                              __nv_bfloat16* __restrict__ dh,
                              __nv_bfloat16* __restrict__ dl, int K)
{
    int b = blockIdx.y;
    size_t tot = (size_t)K * 128;
    const float* s = src + (size_t)b * tot;
    __nv_bfloat16* h = dh + (size_t)b * tot;
    __nv_bfloat16* l = dl + (size_t)b * tot;
    for (size_t idx = blockIdx.x * (size_t)blockDim.x + threadIdx.x; idx < tot;
         idx += (size_t)gridDim.x * blockDim.x) {
        int k = (int)(idx >> 7), n = (int)(idx & 127);
        float v = s[idx];
        __nv_bfloat16 hi = __float2bfloat16(v);
        float lo = v - __bfloat162float(hi);
        h[(size_t)n*K + k] = hi;
        l[(size_t)n*K + k] = __float2bfloat16(lo);
    }
}

// ---------------- mma.sync bf16x3 GEMM ----------------
// C[M,128] = epi(A[M,K] @ W[K,128]); A from fp32 (convert) or pre-split bf16 (cp.async)
__global__ __launch_bounds__(256) void gemm_mma(
    const float* __restrict__ A,                        // fp32 A (or null)
    const __nv_bfloat16* __restrict__ A16h,
    const __nv_bfloat16* __restrict__ A16l,             // bf16 A (or null)
    const __nv_bfloat16* __restrict__ Bh,
    const __nv_bfloat16* __restrict__ Bl,               // [128 n][K]
    const float* __restrict__ bias,
    const float* __restrict__ mulW,                     // [6,128]: v *= rbf@mulW
    const float* __restrict__ addp,
    const float* __restrict__ scW,                      // [6,128]: red (rbf@scW)*v
    const int* __restrict__ sc_idx, float* __restrict__ sc_out,
    const float* __restrict__ rbf,                      // [M,6]
    float* __restrict__ C,                              // fp32 out (or null)
    __nv_bfloat16* __restrict__ C16h,
    __nv_bfloat16* __restrict__ C16l,                   // bf16 split out (or null)
    int M, int K, int act)
{
    extern __shared__ char smraw[];
    char* sm = (char*)(((uintptr_t)smraw + 1023) & ~(uintptr_t)1023);
    uint32_t smb = smem_u32(sm);
    float* wmul_s = (float*)(sm + SM_WMUL);
    float* wsc_s  = (float*)(sm + SM_WSC);
    float* rbf6   = (float*)(sm + SM_RBF6);
    float* bias_s = (float*)(sm + SM_BIAS);

    int tid = threadIdx.x;
    int lane = tid & 31;
    int wid = tid >> 5;
    int bm = blockIdx.x * 128;
    int need_rbf = (mulW != nullptr) || (scW != nullptr);

    for (int k = tid; k < NR*E; k += 256) {
        if (mulW) wmul_s[k] = mulW[k];
        if (scW)  wsc_s[k]  = scW[k];
    }
    for (int k = tid; k < E; k += 256) bias_s[k] = bias ? bias[k] : 0.f;
    if (need_rbf && tid < 128) {
        int g = bm + tid; if (g >= M) g = M - 1;
        #pragma unroll
        for (int q = 0; q < NR; q++) rbf6[tid*NR + q] = rbf[(size_t)g*NR + q];
    }
    __syncthreads();

    // warp tiling: 4 m-warps x 2 n-warps; warp tile 32m x 64n
    int wm = (wid & 3) * 32;
    int wn = (wid >> 2) * 64;
    int lq = lane >> 2;
    int lr4 = lane & 3;
    int r  = lane & 7;
    int mi = lane >> 3;
    uint32_t AHb = smb + SM_AH + (uint32_t)((wm + (mi&1)*8 + r) * 128);
    uint32_t ALb = AHb + TILE;
    int a_chsel = mi >> 1;
    uint32_t BHb = smb + SM_BH + (uint32_t)((wn + ((mi>>1)&1)*8 + r) * 128);
    uint32_t BLb = BHb + TILE;
    int b_chsel = mi & 1;

    float acc[2][8][4];
    #pragma unroll
    for (int a0 = 0; a0 < 2; a0++)
        #pragma unroll
        for (int b0 = 0; b0 < 8; b0++)
            #pragma unroll
            for (int c0 = 0; c0 < 4; c0++) acc[a0][b0][c0] = 0.f;

    int nch = K >> 6;
    for (int c = 0; c < nch; c++) {
        int kc = c << 6;

        // ---- B tiles via cp.async (always pre-split bf16) ----
        #pragma unroll
        for (int u = 0; u < 8; u++) {
            int f = u*256 + tid;
            int which = f >> 10;
            int g2 = f & 1023;
            int n = g2 >> 3, ch = g2 & 7;
            const __nv_bfloat16* src = (which ? Bl : Bh) + (size_t)n*K + kc + ch*8;
            uint32_t dst = smb + (which ? SM_BL : SM_BH)
                         + (uint32_t)(n*128 + ((ch ^ (n & 7)) << 4));
            CP_ASYNC16(dst, src);
        }
        if (A16h) {
            // ---- A tiles via cp.async (pre-split bf16) ----
            #pragma unroll
            for (int u = 0; u < 8; u++) {
                int f = u*256 + tid;
                int which = f >> 10;
                int g2 = f & 1023;
                int rr = g2 >> 3, ch = g2 & 7;
                int g = bm + rr; if (g >= M) g = M - 1;
                const __nv_bfloat16* src = (which ? A16l : A16h) + (size_t)g*K + kc + ch*8;
                uint32_t dst = smb + (which ? SM_AL : SM_AH)
                             + (uint32_t)(rr*128 + ((ch ^ (rr & 7)) << 4));
                CP_ASYNC16(dst, src);
            }
            CP_COMMIT();
            CP_WAIT0();
        } else {
            CP_COMMIT();
            // ---- A tiles: fp32 -> bf16 hi/lo, swizzled stores ----
            #pragma unroll
            for (int u = 0; u < 4; u++) {
                int f = u*256 + tid;
                int rr = f >> 3, ch = f & 7;
                int g = bm + rr;
                int k = kc + ch*8;
                float v[8];
                if (g < M) {
                    float4 p0 = *(const float4*)&A[(size_t)g*K + k];
                    float4 p1 = *(const float4*)&A[(size_t)g*K + k + 4];
                    v[0]=p0.x; v[1]=p0.y; v[2]=p0.z; v[3]=p0.w;
                    v[4]=p1.x; v[5]=p1.y; v[6]=p1.z; v[7]=p1.w;
                } else {
                    #pragma unroll
                    for (int e2 = 0; e2 < 8; e2++) v[e2] = 0.f;
                }
                uint4 hb, lb;
                float l0, l1;
                hb.x = pack_bf16_hi(v[0], v[1], l0, l1); lb.x = pack_bf16(l0, l1);
                hb.y = pack_bf16_hi(v[2], v[3], l0, l1); lb.y = pack_bf16(l0, l1);
                hb.z = pack_bf16_hi(v[4], v[5], l0, l1); lb.z = pack_bf16(l0, l1);
                hb.w = pack_bf16_hi(v[6], v[7], l0, l1); lb.w = pack_bf16(l0, l1);
                uint32_t sw = (uint32_t)(rr*128 + ((ch ^ (rr & 7)) << 4));
                *(uint4*)(sm + SM_AH + sw) = hb;
                *(uint4*)(sm + SM_AL + sw) = lb;
            }
            CP_WAIT0();
        }
        __syncthreads();

        // ---- consume: ldmatrix + mma (R4-validated fragment logic) ----
        #pragma unroll
        for (int ks = 0; ks < 4; ks++) {
            uint32_t aswz = (uint32_t)(((2*ks + a_chsel) ^ r) << 4);
            uint32_t bswz = (uint32_t)(((2*ks + b_chsel) ^ r) << 4);
            uint32_t ah[2][4], al[2][4];
            LDSM4(ah[0], AHb + aswz);
            LDSM4(ah[1], AHb + 2048 + aswz);
            LDSM4(al[0], ALb + aswz);
            LDSM4(al[1], ALb + 2048 + aswz);
            #pragma unroll
            for (int p = 0; p < 4; p++) {
                uint32_t bh[4], bl[4];
                LDSM4(bh, BHb + (uint32_t)(p*2048) + bswz);
                LDSM4(bl, BLb + (uint32_t)(p*2048) + bswz);
                #pragma unroll
                for (int mt = 0; mt < 2; mt++) {
                    MMA_BF16(acc[mt][2*p+0], ah[mt], bh[0], bh[1]);
                    MMA_BF16(acc[mt][2*p+0], ah[mt], bl[0], bl[1]);
                    MMA_BF16(acc[mt][2*p+0], al[mt], bh[0], bh[1]);
                    MMA_BF16(acc[mt][2*p+1], ah[mt], bh[2], bh[3]);
                    MMA_BF16(acc[mt][2*p+1], ah[mt], bl[2], bl[3]);
                    MMA_BF16(acc[mt][2*p+1], al[mt], bh[2], bh[3]);
                }
            }
        }
        __syncthreads();
    }

    // ---- epilogue ----
    #pragma unroll
    for (int mt = 0; mt < 2; mt++) {
        int lrbase = wm + mt*16 + lq;
        #pragma unroll
        for (int h = 0; h < 2; h++) {
            int lrow = lrbase + h*8;
            int row = bm + lrow;
            if (row >= M) continue;
            int asc = scW ? sc_idx[row] : 0;
            #pragma unroll
            for (int nt = 0; nt < 8; nt++) {
                int col = wn + nt*8 + lr4*2;
                float v0 = acc[mt][nt][2*h+0] + bias_s[col];
                float v1 = acc[mt][nt][2*h+1] + bias_s[col+1];
                if (act) { v0 = silu_f(v0); v1 = silu_f(v1); }
                if (mulW) {
                    float d0 = 0.f, d1 = 0.f;
                    #pragma unroll
                    for (int q = 0; q < NR; q++) {
                        float rq = rbf6[lrow*NR + q];
                        d0 += rq * wmul_s[q*E + col];
                        d1 += rq * wmul_s[q*E + col + 1];
                    }
                    v0 *= d0; v1 *= d1;
                }
                if (addp) {
                    float2 av = *(const float2*)&addp[(size_t)row*128 + col];
                    v0 += av.x; v1 += av.y;
                }
                if (C) *(float2*)&C[(size_t)row*128 + col] = make_float2(v0, v1);
                if (C16h) {
                    float l0, l1;
                    uint32_t hb = pack_bf16_hi(v0, v1, l0, l1);
                    uint32_t lb = pack_bf16(l0, l1);
                    *(uint32_t*)&C16h[(size_t)row*128 + col] = hb;
                    *(uint32_t*)&C16l[(size_t)row*128 + col] = lb;
                }
                if (scW) {
                    float g0 = 0.f, g1 = 0.f;
                    #pragma unroll
                    for (int q = 0; q < NR; q++) {
                        float rq = rbf6[lrow*NR + q];
                        g0 += rq * wsc_s[q*E + col];
                        g1 += rq * wsc_s[q*E + col + 1];
                    }
                    RED2(&sc_out[(size_t)asc*128 + col], g0*v0, g1*v1);
                }
            }
        }
    }
}

// ---------------- triplet messages + scatter to edges ----------------
__global__ __launch_bounds__(256) void triplet_kernel(
    const float* __restrict__ xkj,
    const float* __restrict__ cosik,
    const int* __restrict__ idx_kj,
    const int* __restrict__ idx_ji,
    const float* __restrict__ Wabf,       // [7,128]
    float* __restrict__ aggr)
{
    __shared__ float ws[NABF*E];
    for (int k = threadIdx.x; k < NABF*E; k += 256) ws[k] = Wabf[k];
    __syncthreads();
    int lane = threadIdx.x & 31;
    int warp = (blockIdx.x * 256 + threadIdx.x) >> 5;
    int nwarps = (gridDim.x * 256) >> 5;
    int c = lane << 2;
    for (int t = warp; t < TT; t += nwarps) {
        int ekj = idx_kj[t];
        int eji = idx_ji[t];
        float x = fminf(1.f, fmaxf(-1.f, cosik[t]));
        // cos(k*acos(x)) = T_k(x), Chebyshev recurrence (exact identity)
        float a0 = 1.f, a1 = x;
        float a2 = 2.f*x*a1 - a0;
        float a3 = 2.f*x*a2 - a1;
        float a4 = 2.f*x*a3 - a2;
        float a5 = 2.f*x*a4 - a3;
        float a6 = 2.f*x*a5 - a4;
        float4 xv = *(const float4*)&xkj[(size_t)ekj*128 + c];
        float m[4];
        #pragma unroll
        for (int j = 0; j < 4; j++) {
            int cc = c + j;
            m[j] = a0*ws[cc] + a1*ws[E+cc] + a2*ws[2*E+cc] + a3*ws[3*E+cc]
                 + a4*ws[4*E+cc] + a5*ws[5*E+cc] + a6*ws[6*E+cc];
        }
        RED4(&aggr[(size_t)eji*128 + c], xv.x*m[0], xv.y*m[1], xv.z*m[2], xv.w*m[3]);
    }
}

// ---------------- final molecule reduction ----------------
__global__ void final_kernel(const float* __restrict__ ro,
                             const float* __restrict__ rs,
                             const int* __restrict__ bseg,
                             const float* __restrict__ cmp_p,
                             const float* __restrict__ csg_p,
                             float* __restrict__ out)
{
    float cmp = cmp_p[0], csg = csg_p[0];
    size_t total = (size_t)NA * 32;
    for (size_t idx = blockIdx.x * (size_t)blockDim.x + threadIdx.x; idx < total;
         idx += (size_t)gridDim.x * blockDim.x) {
        int a = (int)(idx >> 5);
        int c = (int)(idx & 31) << 2;
        int m = bseg[a];
        float4 o = *(const float4*)&ro[(size_t)a*128 + c];
        float4 s = *(const float4*)&rs[(size_t)a*128 + c];
        RED4(&out[(size_t)m*128 + c],
             cmp*o.x + csg*s.x, cmp*o.y + csg*s.y,
             cmp*o.z + csg*s.z, cmp*o.w + csg*s.w);
    }
}

// ---------------- host orchestration ----------------
extern "C" void kernel_launch(void* const* d_in, const int* in_sizes, int n_in,
                              void* d_out, int out_size)
{
    const int*   Z      = (const int*)  d_in[0];
    const float* R      = (const float*)d_in[1];
    const int*   bseg   = (const int*)  d_in[2];
    const int*   idx_i  = (const int*)  d_in[3];
    const int*   idx_j  = (const int*)  d_in[4];
    const int*   idx_kj = (const int*)  d_in[5];
    const int*   idx_ji = (const int*)  d_in[6];
    const float* cosik  = (const float*)d_in[7];
    const float* emb    = (const float*)d_in[8];
    const float* Wrbf   = (const float*)d_in[9];
    const float* Wemb   = (const float*)d_in[10];
    const float* bemb   = (const float*)d_in[11];
    const float* Worbf  = (const float*)d_in[12];
    const float* Wo1    = (const float*)d_in[13];
    const float* bo1    = (const float*)d_in[14];
    const float* Wout   = (const float*)d_in[15];
    const float* Wid1   = (const float*)d_in[16];
    const float* bid1   = (const float*)d_in[17];
    const float* Wid2   = (const float*)d_in[18];
    const float* Wji    = (const float*)d_in[19];
    const float* bji    = (const float*)d_in[20];
    const float* Wkj    = (const float*)d_in[21];
    const float* bkj    = (const float*)d_in[22];
    const float* Wirbf  = (const float*)d_in[23];
    const float* Wabf   = (const float*)d_in[24];
    const float* Wres   = (const float*)d_in[25];
    const float* bres   = (const float*)d_in[26];
    const float* cmp    = (const float*)d_in[27];
    const float* csg    = (const float*)d_in[28];
    float* out = (float*)d_out;

    cudaFuncSetAttribute(gemm_mma, cudaFuncAttributeMaxDynamicSharedMemorySize, SMEM_DYN);

    float* buf = nullptr;
    cudaGetSymbolAddress((void**)&buf, g_buf);
    float* RBF   = buf + OFF_RBF;
    __nv_bfloat16* CATH = (__nv_bfloat16*)(buf + OFF_CATH);
    __nv_bfloat16* CATL = (__nv_bfloat16*)(buf + OFF_CATL);
    __nv_bfloat16* XH   = (__nv_bfloat16*)(buf + OFF_XH);
    __nv_bfloat16* XL   = (__nv_bfloat16*)(buf + OFF_XL);
    float* XKJ   = buf + OFF_XKJ;
    float* AGGR  = buf + OFF_AGGR;
    float* PA    = buf + OFF_PA;
    float* HAT   = buf + OFF_HAT;
    float* ROUT  = buf + OFF_ROUT;
    float* RSING = buf + OFF_RSING;
    float* STMP  = buf + OFF_STMP;
    float* X0    = buf + OFF_X0;
    float* WT    = buf + OFF_WT;

    #define BF(off) ((__nv_bfloat16*)(WT + (off)))

    const int GE = (EG + 127) / 128;   // 2344
    const int GA = (NA + 127) / 128;   // 157

    // ---- prep ----
    rbf_kernel<<<1024, 256>>>(R, idx_i, idx_j, RBF);
    x0_kernel<<<1024, 256>>>(Z, emb, X0);
    buildcat_kernel<<<4096, 128>>>(Z, idx_i, idx_j, emb, Wrbf, RBF, CATH, CATL);
    {
        dim3 g4(48, 4), g3(48, 3);
        tsplit_kernel<<<dim3(96,1), 256>>>(Wemb, BF(WT_EMB_H), BF(WT_EMB_L), 384);
        tsplit_kernel<<<g4, 256>>>(Wo1,  BF(WT_O1_H),  BF(WT_O1_L),  128);
        tsplit_kernel<<<g4, 256>>>(Wout, BF(WT_OUT_H), BF(WT_OUT_L), 128);
        tsplit_kernel<<<g4, 256>>>(Wid1, BF(WT_ID1_H), BF(WT_ID1_L), 128);
        tsplit_kernel<<<g4, 256>>>(Wid2, BF(WT_ID2_H), BF(WT_ID2_L), 128);
        tsplit_kernel<<<g3, 256>>>(Wji,  BF(WT_JI_H),  BF(WT_JI_L),  128);
        tsplit_kernel<<<g3, 256>>>(Wkj,  BF(WT_KJ_H),  BF(WT_KJ_L),  128);
        tsplit_kernel<<<g3, 256>>>(Wres, BF(WT_RES_H), BF(WT_RES_L), 128);
    }

    // ---- embedding block: X(bf16 split) + fused output-block-0 scatter ----
    cudaMemsetAsync(PA, 0, (size_t)NA*E*sizeof(float));
    gemm_mma<<<GE, 256, SMEM_DYN>>>(nullptr, CATH, CATL,
                                    BF(WT_EMB_H), BF(WT_EMB_L), bemb,
                                    nullptr, nullptr,
                                    Worbf, idx_i, PA, RBF,
                                    nullptr, XH, XL, EG, 384, 1);
    gemm_mma<<<GA, 256, SMEM_DYN>>>(PA, nullptr, nullptr, BF(WT_O1_H), BF(WT_O1_L), bo1,
                                    nullptr, nullptr, nullptr, nullptr, nullptr, nullptr,
                                    HAT, nullptr, nullptr, NA, 128, 1);
    gemm_mma<<<GA, 256, SMEM_DYN>>>(HAT, nullptr, nullptr, BF(WT_OUT_H), BF(WT_OUT_L), nullptr,
                                    nullptr, nullptr, nullptr, nullptr, nullptr, nullptr,
                                    ROUT, nullptr, nullptr, NA, 128, 0);
    gemm_mma<<<GA, 256, SMEM_DYN>>>(X0, nullptr, nullptr, BF(WT_ID1_H), BF(WT_ID1_L), bid1,
                                    nullptr, nullptr, nullptr, nullptr, nullptr, nullptr,
                                    STMP, nullptr, nullptr, NA, 128, 1);
    gemm_mma<<<GA, 256, SMEM_DYN>>>(STMP, nullptr, nullptr, BF(WT_ID2_H), BF(WT_ID2_L), nullptr,
                                    nullptr, nullptr, nullptr, nullptr, nullptr, nullptr,
                                    RSING, nullptr, nullptr, NA, 128, 0);

    for (int i = 0; i < NB; i++) {
        size_t wo = (size_t)i * 128 * 128;          // bf16 element offset
        // x_ji -> AGGR (triplet messages accumulate on top)
        gemm_mma<<<GE, 256, SMEM_DYN>>>(nullptr, XH, XL,
                                        BF(WT_JI_H) + wo, BF(WT_JI_L) + wo, bji + (size_t)i*E,
                                        nullptr, nullptr, nullptr, nullptr, nullptr, nullptr,
                                        AGGR, nullptr, nullptr, EG, 128, 1);
        // x_kj = silu(x@Wkj+b) * (rbf@Wirbf)
        gemm_mma<<<GE, 256, SMEM_DYN>>>(nullptr, XH, XL,
                                        BF(WT_KJ_H) + wo, BF(WT_KJ_L) + wo, bkj + (size_t)i*E,
                                        Wirbf + (size_t)i*NR*E, nullptr,
                                        nullptr, nullptr, nullptr, RBF,
                                        XKJ, nullptr, nullptr, EG, 128, 1);
        triplet_kernel<<<2048, 256>>>(XKJ, cosik, idx_kj, idx_ji,
                                      Wabf + (size_t)i*NABF*E, AGGR);
        cudaMemsetAsync(PA, 0, (size_t)NA*E*sizeof(float));
        // x = h + silu(h@Wres+b) -> XH/XL; fused output-block(i+1) scatter -> PA
        gemm_mma<<<GE, 256, SMEM_DYN>>>(AGGR, nullptr, nullptr,
                                        BF(WT_RES_H) + wo, BF(WT_RES_L) + wo, bres + (size_t)i*E,
                                        nullptr, AGGR,
                                        Worbf + (size_t)(i+1)*NR*E, idx_i, PA, RBF,
                                        nullptr, XH, XL, EG, 128, 1);
        size_t wo1 = (size_t)(i+1) * 128 * 128;
        gemm_mma<<<GA, 256, SMEM_DYN>>>(PA, nullptr, nullptr,
                                        BF(WT_O1_H) + wo1, BF(WT_O1_L) + wo1, bo1 + (size_t)(i+1)*E,
                                        nullptr, nullptr, nullptr, nullptr, nullptr, nullptr,
                                        HAT, nullptr, nullptr, NA, 128, 1);
        gemm_mma<<<GA, 256, SMEM_DYN>>>(HAT, nullptr, nullptr,
                                        BF(WT_OUT_H) + wo1, BF(WT_OUT_L) + wo1, nullptr,
                                        nullptr, ROUT, nullptr, nullptr, nullptr, nullptr,
                                        ROUT, nullptr, nullptr, NA, 128, 0);
        gemm_mma<<<GA, 256, SMEM_DYN>>>(RSING, nullptr, nullptr,
                                        BF(WT_ID1_H) + wo1, BF(WT_ID1_L) + wo1, bid1 + (size_t)(i+1)*E,
                                        nullptr, nullptr, nullptr, nullptr, nullptr, nullptr,
                                        STMP, nullptr, nullptr, NA, 128, 1);
        gemm_mma<<<GA, 256, SMEM_DYN>>>(STMP, nullptr, nullptr,
                                        BF(WT_ID2_H) + wo1, BF(WT_ID2_L) + wo1, nullptr,
                                        nullptr, RSING, nullptr, nullptr, nullptr, nullptr,
                                        RSING, nullptr, nullptr, NA, 128, 0);
    }

    cudaMemsetAsync(out, 0, (size_t)NM*E*sizeof(float));
    final_kernel<<<512, 256>>>(ROUT, RSING, bseg, cmp, csg, out);
}